// round 15
// baseline (speedup 1.0000x reference)
#include <cuda_runtime.h>
#include <math.h>

// out[b,i,j] = pos_biases[j - i + n - 1]
//            + ts_w[ clamp( floor( log(clip(|f32(t[min(i+1,n-1)]) - f32(t[j])|, 1, 1e9)) / 0.301 ), 0, nb ) ]
//
// R13 exact core (biased-trunc __log2f + host-built ulp-exact threshold table
// fused as (thr[k], w[k-1], w[k]); LDS.128 + compare/select per element).
// R14: tile = 8 rows x 1024 cols (4096 blocks) to kill tail-wave quantization
// (2.31 waves @ 2048 blocks -> 4.6 waves, util 77% -> 92%); float4 pos staging.
// rel_err identical: 4.933e-4.

struct ThrTab { float thr[80]; };

// ---------------- specialized kernel: n == 2048 ----------------

__global__ void __launch_bounds__(256, 6)
bias_kernel_2048(const int*   __restrict__ ts,
                 const float* __restrict__ pos,
                 const float* __restrict__ tsw,
                 float*       __restrict__ out,
                 int nb, ThrTab tab) {
    constexpr int N  = 2048;
    constexpr int JW = 1024;                 // columns per tile
    __shared__ float4 s_tab[80];
    __shared__ float  s_pos[JW + 16];

    const int b   = blockIdx.y;
    const int bx  = blockIdx.x;              // 512 tiles: 256 i-tiles x 2 j-tiles
    const int j0  = (bx & 1) * JW;
    const int i0  = (bx >> 1) * 8;
    const int tid = threadIdx.x;
    const int* trow = ts + b * N;

    if (tid < 80) {
        int k = tid;
        float wkm1 = tsw[min(max(k - 1, 0), nb)];
        float wk   = tsw[min(k, nb)];
        s_tab[k] = make_float4(tab.thr[k], wkm1, wk, 0.0f);
    }
    // pos window: global index = pbase + local, local in [0, JW+16)
    const int pbase = j0 + (N - 8) - i0;     // j0 + 2040 - i0, always >= 0, mult of 4
    #pragma unroll
    for (int u = 0; u < 2; ++u) {
        int idx4 = tid * 4 + u * 1024;
        if (idx4 < JW + 16) {
            int g = pbase + idx4;
            if (g + 3 <= 2 * N - 2) {
                *reinterpret_cast<float4*>(s_pos + idx4) =
                    *reinterpret_cast<const float4*>(pos + g);
            } else {
                #pragma unroll
                for (int e = 0; e < 4; ++e)
                    s_pos[idx4 + e] = (g + e <= 2 * N - 2) ? pos[g + e] : 0.0f;
            }
        }
    }
    __syncthreads();

    float tnr[8];
    #pragma unroll
    for (int r = 0; r < 8; ++r) tnr[r] = (float)__ldg(&trow[min(i0 + r + 1, N - 1)]);

    const int jj = tid * 4;                  // local column, [0, 1024)
    int4 ti = *reinterpret_cast<const int4*>(trow + j0 + jj);
    const float tv0 = (float)ti.x, tv1 = (float)ti.y,
                tv2 = (float)ti.z, tv3 = (float)ti.w;
    float4 p0 = *reinterpret_cast<const float4*>(s_pos + jj);
    float4 p1 = *reinterpret_cast<const float4*>(s_pos + jj + 4);
    float4 p2 = *reinterpret_cast<const float4*>(s_pos + jj + 8);
    const float pw[12] = {p0.x, p0.y, p0.z, p0.w,
                          p1.x, p1.y, p1.z, p1.w,
                          p2.x, p2.y, p2.z, p2.w};

    float* op = out + ((size_t)b * N + i0) * (size_t)N + j0 + jj;

    #pragma unroll
    for (int r = 0; r < 8; ++r) {
        const float tn = tnr[r];
        float w0, w1, w2, w3;
        {
            float x = fmaxf(fabsf(tn - tv0), 1.0f);
            float q = fmaf(__log2f(x), 2.3028145f, 1.25e-4f);
            float4 te = s_tab[(int)q];
            w0 = (x < te.x) ? te.y : te.z;
        }
        {
            float x = fmaxf(fabsf(tn - tv1), 1.0f);
            float q = fmaf(__log2f(x), 2.3028145f, 1.25e-4f);
            float4 te = s_tab[(int)q];
            w1 = (x < te.x) ? te.y : te.z;
        }
        {
            float x = fmaxf(fabsf(tn - tv2), 1.0f);
            float q = fmaf(__log2f(x), 2.3028145f, 1.25e-4f);
            float4 te = s_tab[(int)q];
            w2 = (x < te.x) ? te.y : te.z;
        }
        {
            float x = fmaxf(fabsf(tn - tv3), 1.0f);
            float q = fmaf(__log2f(x), 2.3028145f, 1.25e-4f);
            float4 te = s_tab[(int)q];
            w3 = (x < te.x) ? te.y : te.z;
        }
        float4 o;
        o.x = w0 + pw[7 - r];
        o.y = w1 + pw[8 - r];
        o.z = w2 + pw[9 - r];
        o.w = w3 + pw[10 - r];
        *reinterpret_cast<float4*>(op + r * N) = o;   // immediate offset
    }
}

// ---------------- generic fallback (R6) ----------------

__global__ void __launch_bounds__(256)
bias_kernel_gen(const int*   __restrict__ ts,
                const float* __restrict__ pos,
                const float* __restrict__ tsw,
                float*       __restrict__ out,
                int n, int nb, ThrTab tab) {
    extern __shared__ float sm[];
    float4* s_tab = (float4*)sm;
    float*  s_pos = sm + 320;

    const int b   = blockIdx.y;
    const int i0  = blockIdx.x * 8;
    const int tid = threadIdx.x;
    const int* trow = ts + (size_t)b * n;

    if (tid < 80) {
        int k = tid;
        float wkm1 = tsw[min(max(k - 1, 0), nb)];
        float wk   = tsw[min(k, nb)];
        s_tab[k] = make_float4(tab.thr[k], wkm1, wk, 0.0f);
    }
    const int pbase = n - 8 - i0;
    for (int idx = tid; idx < n + 16; idx += 256) {
        int g = pbase + idx;
        s_pos[idx] = (g >= 0 && g <= 2 * n - 2) ? pos[g] : 0.0f;
    }
    __syncthreads();

    float tnr[8];
    #pragma unroll
    for (int r = 0; r < 8; ++r) tnr[r] = (float)__ldg(&trow[min(i0 + r + 1, n - 1)]);

    const bool full = (i0 + 8 <= n);
    float* oblk = out + ((size_t)b * n + i0) * (size_t)n;

    for (int jj = tid * 4; jj < n; jj += 1024) {
        int4 ti = *reinterpret_cast<const int4*>(trow + jj);
        const float tv0 = (float)ti.x, tv1 = (float)ti.y,
                    tv2 = (float)ti.z, tv3 = (float)ti.w;
        float4 p0 = *reinterpret_cast<const float4*>(s_pos + jj);
        float4 p1 = *reinterpret_cast<const float4*>(s_pos + jj + 4);
        float4 p2 = *reinterpret_cast<const float4*>(s_pos + jj + 8);
        const float pw[12] = {p0.x, p0.y, p0.z, p0.w,
                              p1.x, p1.y, p1.z, p1.w,
                              p2.x, p2.y, p2.z, p2.w};
        float* op = oblk + jj;

        #pragma unroll
        for (int r = 0; r < 8; ++r) {
            const float tn = tnr[r];
            float w0, w1, w2, w3;
            {
                float x = fmaxf(fabsf(tn - tv0), 1.0f);
                float q = fmaf(__log2f(x), 2.3028145f, 1.25e-4f);
                float4 te = s_tab[(int)q];
                w0 = (x < te.x) ? te.y : te.z;
            }
            {
                float x = fmaxf(fabsf(tn - tv1), 1.0f);
                float q = fmaf(__log2f(x), 2.3028145f, 1.25e-4f);
                float4 te = s_tab[(int)q];
                w1 = (x < te.x) ? te.y : te.z;
            }
            {
                float x = fmaxf(fabsf(tn - tv2), 1.0f);
                float q = fmaf(__log2f(x), 2.3028145f, 1.25e-4f);
                float4 te = s_tab[(int)q];
                w2 = (x < te.x) ? te.y : te.z;
            }
            {
                float x = fmaxf(fabsf(tn - tv3), 1.0f);
                float q = fmaf(__log2f(x), 2.3028145f, 1.25e-4f);
                float4 te = s_tab[(int)q];
                w3 = (x < te.x) ? te.y : te.z;
            }
            if (full || i0 + r < n) {
                float4 o;
                o.x = w0 + pw[7 - r];
                o.y = w1 + pw[8 - r];
                o.z = w2 + pw[9 - r];
                o.w = w3 + pw[10 - r];
                *reinterpret_cast<float4*>(op) = o;
            }
            op += n;
        }
    }
}

static void build_thresholds_host(ThrTab* tab) {
    typedef union { float f; unsigned u; } FU;
    for (int k = 0; k < 80; ++k) {
        if (k == 0) { tab->thr[0] = 1.0f; continue; }
        volatile float kb = 0.301f;                  // force f32 division semantics
        FU l; l.f = (float)(0.301 * (double)k);
        while (!((float)(l.f / kb) >= (float)k)) l.u += 1u;
        for (;;) {
            FU p; p.u = l.u - 1u;
            if ((float)(p.f / kb) >= (float)k) l.u = p.u; else break;
        }
        FU x; x.f = (float)exp((double)l.f);
        while (!((float)log((double)x.f) >= l.f)) x.u += 1u;
        for (;;) {
            FU p; p.u = x.u - 1u;
            if ((float)log((double)p.f) >= l.f) x.u = p.u; else break;
        }
        tab->thr[k] = x.f;
    }
}

extern "C" void kernel_launch(void* const* d_in, const int* in_sizes, int n_in,
                              void* d_out, int out_size) {
    const int*   ts  = (const int*)d_in[0];     // timestamps (B*N) int32
    const float* pos = (const float*)d_in[1];   // pos_biases (2N-1) f32
    const float* tsw = (const float*)d_in[2];   // ts_w (nb+1) f32

    const int n  = (in_sizes[1] + 1) / 2;
    const int B  = in_sizes[0] / n;
    const int nb = in_sizes[2] - 1;

    ThrTab tab;
    build_thresholds_host(&tab);

    if (n == 2048) {
        dim3 grid(512, B);                    // 256 i-tiles x 2 j-tiles
        bias_kernel_2048<<<grid, 256>>>(ts, pos, tsw, (float*)d_out, nb, tab);
    } else {
        size_t smem = (size_t)(320 + n + 16) * sizeof(float);
        dim3 grid((n + 7) / 8, B);
        bias_kernel_gen<<<grid, 256, smem>>>(ts, pos, tsw, (float*)d_out, n, nb, tab);
    }
}

// round 16
// speedup vs baseline: 1.0756x; 1.0756x over previous
#include <cuda_runtime.h>
#include <math.h>

// out[b,i,j] = pos_biases[j - i + n - 1]
//            + ts_w[ clamp( floor( log(clip(|f32(t[min(i+1,n-1)]) - f32(t[j])|, 1, 1e9)) / 0.301 ), 0, nb ) ]
//
// R15: MUFU-free exact bucketing. For x >= 1:
//   k0 = umulhi(float_bits(x) - 0x3F800000, 1179)   // floor of an UNDER-estimate
// underestimates q = ln(x)/0.301 by at most 0.202 and never overestimates,
// so the true bucket is k0 or k0+1. s_tab[k0] = (thr[k0+1], w[k0], w[k0+1]);
// one exact compare x >= thr[k0+1] selects it. Thresholds thr[k] (smallest f32
// with floor(fdiv_rn(log_rn(x),0.301f)) >= k) host-built, ulp-exact.
// Bucket selection set identical to R6-R14 -> rel_err 4.933e-4 unchanged.

struct ThrTab { float thr[81]; };

// ---------------- specialized kernel: n == 2048 ----------------

__global__ void __launch_bounds__(256, 6)
bias_kernel_2048(const int*   __restrict__ ts,
                 const float* __restrict__ pos,
                 const float* __restrict__ tsw,
                 float*       __restrict__ out,
                 int nb, ThrTab tab) {
    constexpr int N = 2048;
    __shared__ float4 s_tab[80];
    __shared__ float  s_pos[N + 16];

    const int b   = blockIdx.y;
    const int i0  = blockIdx.x * 8;           // grid.x = 256, exact
    const int tid = threadIdx.x;
    const int* trow = ts + b * N;

    if (tid < 80) {
        int k = tid;
        s_tab[k] = make_float4(tab.thr[k + 1],
                               tsw[min(k, nb)],
                               tsw[min(k + 1, nb)], 0.0f);
    }
    const int pbase = N - 8 - i0;             // >= 0
    #pragma unroll
    for (int u = 0; u < (N + 16 + 255) / 256; ++u) {
        int idx = tid + u * 256;
        if (idx < N + 16) {
            int g = pbase + idx;
            s_pos[idx] = (g <= 2 * N - 2) ? pos[g] : 0.0f;
        }
    }
    __syncthreads();

    float tnr[8];
    #pragma unroll
    for (int r = 0; r < 8; ++r) tnr[r] = (float)__ldg(&trow[min(i0 + r + 1, N - 1)]);

    float* oblk = out + ((size_t)b * N + i0) * (size_t)N;

    #pragma unroll 1
    for (int half = 0; half < 2; ++half) {
        const int jj = tid * 4 + half * 1024;
        int4 ti = *reinterpret_cast<const int4*>(trow + jj);
        const float tv0 = (float)ti.x, tv1 = (float)ti.y,
                    tv2 = (float)ti.z, tv3 = (float)ti.w;
        float4 p0 = *reinterpret_cast<const float4*>(s_pos + jj);
        float4 p1 = *reinterpret_cast<const float4*>(s_pos + jj + 4);
        float4 p2 = *reinterpret_cast<const float4*>(s_pos + jj + 8);
        const float pw[12] = {p0.x, p0.y, p0.z, p0.w,
                              p1.x, p1.y, p1.z, p1.w,
                              p2.x, p2.y, p2.z, p2.w};
        float* op = oblk + jj;

        #pragma unroll
        for (int r = 0; r < 8; ++r) {
            const float tn = tnr[r];
            float w0, w1, w2, w3;
            {
                float x = fmaxf(fabsf(tn - tv0), 1.0f);
                int k0 = __umulhi(__float_as_uint(x) - 0x3F800000u, 1179u);
                float4 te = s_tab[k0];
                w0 = (x >= te.x) ? te.z : te.y;
            }
            {
                float x = fmaxf(fabsf(tn - tv1), 1.0f);
                int k0 = __umulhi(__float_as_uint(x) - 0x3F800000u, 1179u);
                float4 te = s_tab[k0];
                w1 = (x >= te.x) ? te.z : te.y;
            }
            {
                float x = fmaxf(fabsf(tn - tv2), 1.0f);
                int k0 = __umulhi(__float_as_uint(x) - 0x3F800000u, 1179u);
                float4 te = s_tab[k0];
                w2 = (x >= te.x) ? te.z : te.y;
            }
            {
                float x = fmaxf(fabsf(tn - tv3), 1.0f);
                int k0 = __umulhi(__float_as_uint(x) - 0x3F800000u, 1179u);
                float4 te = s_tab[k0];
                w3 = (x >= te.x) ? te.z : te.y;
            }
            float4 o;
            o.x = w0 + pw[7 - r];
            o.y = w1 + pw[8 - r];
            o.z = w2 + pw[9 - r];
            o.w = w3 + pw[10 - r];
            *reinterpret_cast<float4*>(op + r * N) = o;   // immediate offset
        }
    }
}

// ---------------- generic fallback ----------------

__global__ void __launch_bounds__(256)
bias_kernel_gen(const int*   __restrict__ ts,
                const float* __restrict__ pos,
                const float* __restrict__ tsw,
                float*       __restrict__ out,
                int n, int nb, ThrTab tab) {
    extern __shared__ float sm[];
    float4* s_tab = (float4*)sm;
    float*  s_pos = sm + 320;

    const int b   = blockIdx.y;
    const int i0  = blockIdx.x * 8;
    const int tid = threadIdx.x;
    const int* trow = ts + (size_t)b * n;

    if (tid < 80) {
        int k = tid;
        s_tab[k] = make_float4(tab.thr[k + 1],
                               tsw[min(k, nb)],
                               tsw[min(k + 1, nb)], 0.0f);
    }
    const int pbase = n - 8 - i0;
    for (int idx = tid; idx < n + 16; idx += 256) {
        int g = pbase + idx;
        s_pos[idx] = (g >= 0 && g <= 2 * n - 2) ? pos[g] : 0.0f;
    }
    __syncthreads();

    float tnr[8];
    #pragma unroll
    for (int r = 0; r < 8; ++r) tnr[r] = (float)__ldg(&trow[min(i0 + r + 1, n - 1)]);

    const bool full = (i0 + 8 <= n);
    float* oblk = out + ((size_t)b * n + i0) * (size_t)n;

    for (int jj = tid * 4; jj < n; jj += 1024) {
        int4 ti = *reinterpret_cast<const int4*>(trow + jj);
        const float tv[4] = {(float)ti.x, (float)ti.y, (float)ti.z, (float)ti.w};
        float4 p0 = *reinterpret_cast<const float4*>(s_pos + jj);
        float4 p1 = *reinterpret_cast<const float4*>(s_pos + jj + 4);
        float4 p2 = *reinterpret_cast<const float4*>(s_pos + jj + 8);
        const float pw[12] = {p0.x, p0.y, p0.z, p0.w,
                              p1.x, p1.y, p1.z, p1.w,
                              p2.x, p2.y, p2.z, p2.w};
        float* op = oblk + jj;

        #pragma unroll
        for (int r = 0; r < 8; ++r) {
            const float tn = tnr[r];
            float w[4];
            #pragma unroll
            for (int e = 0; e < 4; ++e) {
                float x = fminf(fmaxf(fabsf(tn - tv[e]), 1.0f), 1e9f);  // full clip
                int k0 = __umulhi(__float_as_uint(x) - 0x3F800000u, 1179u);
                float4 te = s_tab[k0];
                w[e] = (x >= te.x) ? te.z : te.y;
            }
            if (full || i0 + r < n) {
                float4 o;
                o.x = w[0] + pw[7 - r];
                o.y = w[1] + pw[8 - r];
                o.z = w[2] + pw[9 - r];
                o.w = w[3] + pw[10 - r];
                *reinterpret_cast<float4*>(op) = o;
            }
            op += n;
        }
    }
}

static void build_thresholds_host(ThrTab* tab) {
    typedef union { float f; unsigned u; } FU;
    for (int k = 0; k < 81; ++k) {
        if (k == 0) { tab->thr[0] = 1.0f; continue; }
        volatile float kb = 0.301f;                  // force f32 division semantics
        FU l; l.f = (float)(0.301 * (double)k);
        while (!((float)(l.f / kb) >= (float)k)) l.u += 1u;
        for (;;) {
            FU p; p.u = l.u - 1u;
            if ((float)(p.f / kb) >= (float)k) l.u = p.u; else break;
        }
        FU x; x.f = (float)exp((double)l.f);
        while (!((float)log((double)x.f) >= l.f)) x.u += 1u;
        for (;;) {
            FU p; p.u = x.u - 1u;
            if ((float)log((double)p.f) >= l.f) x.u = p.u; else break;
        }
        tab->thr[k] = x.f;
    }
}

extern "C" void kernel_launch(void* const* d_in, const int* in_sizes, int n_in,
                              void* d_out, int out_size) {
    const int*   ts  = (const int*)d_in[0];     // timestamps (B*N) int32
    const float* pos = (const float*)d_in[1];   // pos_biases (2N-1) f32
    const float* tsw = (const float*)d_in[2];   // ts_w (nb+1) f32

    const int n  = (in_sizes[1] + 1) / 2;
    const int B  = in_sizes[0] / n;
    const int nb = in_sizes[2] - 1;

    ThrTab tab;
    build_thresholds_host(&tab);

    if (n == 2048) {
        dim3 grid(256, B);                    // R13 tiling: 8 rows x 2048 cols
        bias_kernel_2048<<<grid, 256>>>(ts, pos, tsw, (float*)d_out, nb, tab);
    } else {
        size_t smem = (size_t)(320 + n + 16) * sizeof(float);
        dim3 grid((n + 7) / 8, B);
        bias_kernel_gen<<<grid, 256, smem>>>(ts, pos, tsw, (float*)d_out, n, nb, tab);
    }
}

// round 17
// speedup vs baseline: 1.1635x; 1.0817x over previous
#include <cuda_runtime.h>
#include <math.h>

// out[b,i,j] = pos_biases[j - i + n - 1]
//            + ts_w[ clamp( floor( log(clip(|f32(t[min(i+1,n-1)]) - f32(t[j])|, 1, 1e9)) / 0.301 ), 0, nb ) ]
//
// R16: integer bucket estimate + SPLIT scalar tables (LDS.32 x2, near-broadcast):
//   k0 = umulhi(bits(x) - 0x3F800000, 1179)        // k_true-1 or k_true, never over
//   k  = k0 + (bits(x) >= s_thr[k0])               // exact via ulp-exact threshold bits
//   w  = s_w[k]
// Positive-float uint ordering makes the threshold compare exact in integer.
// Same bucket selection set as R6-R15 -> rel_err 4.933e-4 unchanged.
// R13 tiling (8 rows x 2048 cols, grid 2048) retained.

struct ThrTab { float thr[81]; };

// ---------------- specialized kernel: n == 2048 ----------------

__global__ void __launch_bounds__(256, 6)
bias_kernel_2048(const int*   __restrict__ ts,
                 const float* __restrict__ pos,
                 const float* __restrict__ tsw,
                 float*       __restrict__ out,
                 int nb, ThrTab tab) {
    constexpr int N = 2048;
    __shared__ unsigned s_thr[80];     // bits of thr[k0+1]
    __shared__ float    s_w[96];       // ts_w[min(k, nb)], k = 0..80
    __shared__ float    s_pos[N + 16];

    const int b   = blockIdx.y;
    const int i0  = blockIdx.x * 8;           // grid.x = 256, exact
    const int tid = threadIdx.x;
    const int* trow = ts + b * N;

    if (tid < 80) s_thr[tid] = __float_as_uint(tab.thr[tid + 1]);
    if (tid < 96) s_w[tid]   = tsw[min(min(tid, 80), nb)];
    const int pbase = N - 8 - i0;             // >= 0
    #pragma unroll
    for (int u = 0; u < (N + 16 + 255) / 256; ++u) {
        int idx = tid + u * 256;
        if (idx < N + 16) {
            int g = pbase + idx;
            s_pos[idx] = (g <= 2 * N - 2) ? pos[g] : 0.0f;
        }
    }
    __syncthreads();

    float tnr[8];
    #pragma unroll
    for (int r = 0; r < 8; ++r) tnr[r] = (float)__ldg(&trow[min(i0 + r + 1, N - 1)]);

    float* oblk = out + ((size_t)b * N + i0) * (size_t)N;

    #pragma unroll 1
    for (int half = 0; half < 2; ++half) {
        const int jj = tid * 4 + half * 1024;
        int4 ti = *reinterpret_cast<const int4*>(trow + jj);
        const float tv0 = (float)ti.x, tv1 = (float)ti.y,
                    tv2 = (float)ti.z, tv3 = (float)ti.w;
        float4 p0 = *reinterpret_cast<const float4*>(s_pos + jj);
        float4 p1 = *reinterpret_cast<const float4*>(s_pos + jj + 4);
        float4 p2 = *reinterpret_cast<const float4*>(s_pos + jj + 8);
        const float pw[12] = {p0.x, p0.y, p0.z, p0.w,
                              p1.x, p1.y, p1.z, p1.w,
                              p2.x, p2.y, p2.z, p2.w};
        float* op = oblk + jj;

        #pragma unroll
        for (int r = 0; r < 8; ++r) {
            const float tn = tnr[r];
            float w0, w1, w2, w3;
            {
                float x = fmaxf(fabsf(tn - tv0), 1.0f);
                unsigned xb = __float_as_uint(x);
                int k0 = __umulhi(xb - 0x3F800000u, 1179u);
                int k  = k0 + (xb >= s_thr[k0] ? 1 : 0);
                w0 = s_w[k];
            }
            {
                float x = fmaxf(fabsf(tn - tv1), 1.0f);
                unsigned xb = __float_as_uint(x);
                int k0 = __umulhi(xb - 0x3F800000u, 1179u);
                int k  = k0 + (xb >= s_thr[k0] ? 1 : 0);
                w1 = s_w[k];
            }
            {
                float x = fmaxf(fabsf(tn - tv2), 1.0f);
                unsigned xb = __float_as_uint(x);
                int k0 = __umulhi(xb - 0x3F800000u, 1179u);
                int k  = k0 + (xb >= s_thr[k0] ? 1 : 0);
                w2 = s_w[k];
            }
            {
                float x = fmaxf(fabsf(tn - tv3), 1.0f);
                unsigned xb = __float_as_uint(x);
                int k0 = __umulhi(xb - 0x3F800000u, 1179u);
                int k  = k0 + (xb >= s_thr[k0] ? 1 : 0);
                w3 = s_w[k];
            }
            float4 o;
            o.x = w0 + pw[7 - r];
            o.y = w1 + pw[8 - r];
            o.z = w2 + pw[9 - r];
            o.w = w3 + pw[10 - r];
            *reinterpret_cast<float4*>(op + r * N) = o;   // immediate offset
        }
    }
}

// ---------------- generic fallback ----------------

__global__ void __launch_bounds__(256)
bias_kernel_gen(const int*   __restrict__ ts,
                const float* __restrict__ pos,
                const float* __restrict__ tsw,
                float*       __restrict__ out,
                int n, int nb, ThrTab tab) {
    extern __shared__ float sm[];
    unsigned* s_thr = (unsigned*)sm;          // 80
    float*    s_w   = sm + 80;                // 96
    float*    s_pos = sm + 176;               // n + 16

    const int b   = blockIdx.y;
    const int i0  = blockIdx.x * 8;
    const int tid = threadIdx.x;
    const int* trow = ts + (size_t)b * n;

    if (tid < 80) s_thr[tid] = __float_as_uint(tab.thr[tid + 1]);
    if (tid < 96) s_w[tid]   = tsw[min(min(tid, 80), nb)];
    const int pbase = n - 8 - i0;
    for (int idx = tid; idx < n + 16; idx += 256) {
        int g = pbase + idx;
        s_pos[idx] = (g >= 0 && g <= 2 * n - 2) ? pos[g] : 0.0f;
    }
    __syncthreads();

    float tnr[8];
    #pragma unroll
    for (int r = 0; r < 8; ++r) tnr[r] = (float)__ldg(&trow[min(i0 + r + 1, n - 1)]);

    const bool full = (i0 + 8 <= n);
    float* oblk = out + ((size_t)b * n + i0) * (size_t)n;

    for (int jj = tid * 4; jj < n; jj += 1024) {
        int4 ti = *reinterpret_cast<const int4*>(trow + jj);
        const float tv[4] = {(float)ti.x, (float)ti.y, (float)ti.z, (float)ti.w};
        float4 p0 = *reinterpret_cast<const float4*>(s_pos + jj);
        float4 p1 = *reinterpret_cast<const float4*>(s_pos + jj + 4);
        float4 p2 = *reinterpret_cast<const float4*>(s_pos + jj + 8);
        const float pw[12] = {p0.x, p0.y, p0.z, p0.w,
                              p1.x, p1.y, p1.z, p1.w,
                              p2.x, p2.y, p2.z, p2.w};
        float* op = oblk + jj;

        #pragma unroll
        for (int r = 0; r < 8; ++r) {
            const float tn = tnr[r];
            float w[4];
            #pragma unroll
            for (int e = 0; e < 4; ++e) {
                float x = fminf(fmaxf(fabsf(tn - tv[e]), 1.0f), 1e9f);
                unsigned xb = __float_as_uint(x);
                int k0 = __umulhi(xb - 0x3F800000u, 1179u);
                int k  = k0 + (xb >= s_thr[k0] ? 1 : 0);
                w[e] = s_w[k];
            }
            if (full || i0 + r < n) {
                float4 o;
                o.x = w[0] + pw[7 - r];
                o.y = w[1] + pw[8 - r];
                o.z = w[2] + pw[9 - r];
                o.w = w[3] + pw[10 - r];
                *reinterpret_cast<float4*>(op) = o;
            }
            op += n;
        }
    }
}

static void build_thresholds_host(ThrTab* tab) {
    typedef union { float f; unsigned u; } FU;
    for (int k = 0; k < 81; ++k) {
        if (k == 0) { tab->thr[0] = 1.0f; continue; }
        volatile float kb = 0.301f;                  // force f32 division semantics
        FU l; l.f = (float)(0.301 * (double)k);
        while (!((float)(l.f / kb) >= (float)k)) l.u += 1u;
        for (;;) {
            FU p; p.u = l.u - 1u;
            if ((float)(p.f / kb) >= (float)k) l.u = p.u; else break;
        }
        FU x; x.f = (float)exp((double)l.f);
        while (!((float)log((double)x.f) >= l.f)) x.u += 1u;
        for (;;) {
            FU p; p.u = x.u - 1u;
            if ((float)log((double)p.f) >= l.f) x.u = p.u; else break;
        }
        tab->thr[k] = x.f;
    }
}

extern "C" void kernel_launch(void* const* d_in, const int* in_sizes, int n_in,
                              void* d_out, int out_size) {
    const int*   ts  = (const int*)d_in[0];     // timestamps (B*N) int32
    const float* pos = (const float*)d_in[1];   // pos_biases (2N-1) f32
    const float* tsw = (const float*)d_in[2];   // ts_w (nb+1) f32

    const int n  = (in_sizes[1] + 1) / 2;
    const int B  = in_sizes[0] / n;
    const int nb = in_sizes[2] - 1;

    ThrTab tab;
    build_thresholds_host(&tab);

    if (n == 2048) {
        dim3 grid(256, B);                    // 8 rows x 2048 cols per block
        bias_kernel_2048<<<grid, 256>>>(ts, pos, tsw, (float*)d_out, nb, tab);
    } else {
        size_t smem = (size_t)(176 + n + 16) * sizeof(float);
        dim3 grid((n + 7) / 8, B);
        bias_kernel_gen<<<grid, 256, smem>>>(ts, pos, tsw, (float*)d_out, n, nb, tab);
    }
}